// round 14
// baseline (speedup 1.0000x reference)
#include <cuda_runtime.h>
#include <cuda_bf16.h>
#include <math.h>
#include <stdint.h>

// DelayAndSum: out[b,t] = (1/128) * sum_s x[b, t+d_s, s], zero past T.
// d_s = rint(s*sin(0.5235987755982988)/2) in [0,32].
//
// R14 = R9 champion (8 warps/CTA, per-warp 3-stage x 8 KB cp.async.bulk
// SMEM ring, ring-accumulator compute, 144 CTAs = 9/batch) + L2 prefetch
// running PF chunks ahead of the SMEM ring: DRAM sees ~5 sequential 8 KB
// chunks of demand per stream (vs 2 with the ring alone); bulk copies then
// complete from L2. SMEM stays at 192 KB.

#define NTHREADS  256
#define WPB       8
#define CPB       9                   // CTAs per batch
#define WPBATCH   (WPB * CPB)         // 72
#define BPB       3125                // 32-row blocks per batch (T/32)
#define BASE_BLK  (BPB / WPBATCH)     // 43
#define EXTRA     (BPB % WPBATCH)     // 29
#define CHROWS    16
#define CHBYTES   (CHROWS * 512)      // 8192
#define NSTAGE    3
#define PF        3                   // L2-prefetch distance beyond the ring

#define SM_STAGES   0
#define SM_SOPEN    (WPB * NSTAGE * CHBYTES)          // 196608
#define SM_MBAR     (SM_SOPEN + WPB * 32 * 4)         // 197632
#define SM_TOTAL    (SM_MBAR + WPB * NSTAGE * 8)      // 197824

__device__ __forceinline__ void mbar_wait(uint32_t mbar, uint32_t phase) {
    asm volatile(
        "{\n\t"
        ".reg .pred P1;\n\t"
        "WAIT_LOOP_%=:\n\t"
        "mbarrier.try_wait.parity.acquire.cta.shared::cta.b64 P1, [%0], %1, 0x989680;\n\t"
        "@P1 bra.uni WAIT_DONE_%=;\n\t"
        "bra.uni WAIT_LOOP_%=;\n\t"
        "WAIT_DONE_%=:\n\t"
        "}"
        :: "r"(mbar), "r"(phase) : "memory");
}

__device__ __forceinline__ void l2_prefetch(const void* src) {
    asm volatile("cp.async.bulk.prefetch.L2.global [%0], %1;"
                 :: "l"(src), "r"(CHBYTES) : "memory");
}

__global__ __launch_bounds__(NTHREADS, 1)
void das11_kernel(const float* __restrict__ x, float* __restrict__ out,
                  int T, uint4 cmask)
{
    extern __shared__ char smem[];
    const uint32_t smem_u32 = (uint32_t)__cvta_generic_to_shared(smem);

    const int w  = threadIdx.x >> 5;
    const int m  = threadIdx.x & 31;
    const int c  = blockIdx.x;
    const int b  = c / CPB;
    const int cb = c % CPB;
    const int wb = cb * WPB + w;

    const int start_blk = wb * BASE_BLK + (wb < EXTRA ? wb : EXTRA);
    const int nblk      = BASE_BLK + (wb < EXTRA ? 1 : 0);   // 43 or 44
    const int t0  = start_blk * 32;
    const int t1  = t0 + nblk * 32;
    const int nch = nblk * 2;                     // 16-row chunks

    const float* __restrict__ xb = x + (size_t)b * (size_t)T * 128;
    float* __restrict__ outb = out + (size_t)b * T;
    float* sopen = (float*)(smem + SM_SOPEN);

    const uint32_t mbar0 = smem_u32 + SM_MBAR + w * (NSTAGE * 8);
    const uint32_t stg0  = smem_u32 + SM_STAGES + w * (NSTAGE * CHBYTES);

    // per-lane split mask: bit j set <=> d(4m+j) == m (row t+m), else d==m+1
    uint32_t mword = (m < 8)  ? cmask.x :
                     (m < 16) ? cmask.y :
                     (m < 24) ? cmask.z : cmask.w;
    uint32_t bits = (mword >> ((m & 7) * 4)) & 0xFu;
    const float f0 = (bits & 1u) ? 1.f : 0.f;
    const float f1 = (bits & 2u) ? 1.f : 0.f;
    const float f2 = (bits & 4u) ? 1.f : 0.f;
    const float f3 = (bits & 8u) ? 1.f : 0.f;
    const float inv = 1.0f / 128.0f;

    // init this warp's mbarriers
    if (m == 0) {
        #pragma unroll
        for (int s = 0; s < NSTAGE; ++s)
            asm volatile("mbarrier.init.shared.b64 [%0], %1;"
                         :: "r"(mbar0 + s * 8), "r"(1) : "memory");
    }
    __syncwarp();

    // prologue: fill the 3-stage pipeline + prefetch PF chunks beyond it
    if (m == 0) {
        #pragma unroll
        for (int h = 0; h < NSTAGE; ++h) {
            uint32_t bar = mbar0 + h * 8;
            uint32_t dst = stg0 + h * CHBYTES;
            const void* src = (const void*)(xb + (size_t)(t0 + h * CHROWS) * 128);
            asm volatile("mbarrier.arrive.expect_tx.shared.b64 _, [%0], %1;"
                         :: "r"(bar), "r"(CHBYTES) : "memory");
            asm volatile(
                "cp.async.bulk.shared::cluster.global.mbarrier::complete_tx::bytes "
                "[%0], [%1], %2, [%3];"
                :: "r"(dst), "l"(src), "r"(CHBYTES), "r"(bar) : "memory");
        }
        #pragma unroll
        for (int h = NSTAGE; h < NSTAGE + PF; ++h)
            if (h < nch)
                l2_prefetch((const void*)(xb + (size_t)(t0 + h * CHROWS) * 128));
    }

    float acc = 0.f, fin = 0.f, open_fin = 0.f;

    #pragma unroll 1
    for (int h = 0; h < nch; ++h) {
        const int s  = h % NSTAGE;
        const uint32_t ph = (uint32_t)((h / NSTAGE) & 1);
        mbar_wait(mbar0 + s * 8, ph);

        const float4* sb = (const float4*)(smem + w * (NSTAGE * CHBYTES)
                                                + s * CHBYTES) + m;
        const int kbase = (h & 1) << 4;
        #pragma unroll
        for (int i = 0; i < CHROWS; ++i) {
            float4 v = sb[i * 32];
            float tot = (v.x + v.y) + (v.z + v.w);
            float a = fmaf(v.x, f0, fmaf(v.y, f1, fmaf(v.z, f2, v.w * f3)));
            float cc = tot - a;
            int k = kbase + i;
            int r = (k - m) & 31;
            float u1 = __shfl_sync(0xffffffffu, a, r);
            float u2 = __shfl_sync(0xffffffffu, cc, (r + 31) & 31);
            bool wrap = (r == 0);
            float closed = acc + u2;
            fin = wrap ? closed : fin;
            acc = wrap ? u1 : acc + (u1 + u2);
        }
        __syncwarp();

        // reuse this stage for chunk h+NSTAGE; prefetch chunk h+NSTAGE+PF
        if (h + NSTAGE < nch && m == 0) {
            asm volatile("fence.proxy.async.shared::cta;" ::: "memory");
            uint32_t bar = mbar0 + s * 8;
            uint32_t dst = stg0 + s * CHBYTES;
            const void* src =
                (const void*)(xb + (size_t)(t0 + (h + NSTAGE) * CHROWS) * 128);
            asm volatile("mbarrier.arrive.expect_tx.shared.b64 _, [%0], %1;"
                         :: "r"(bar), "r"(CHBYTES) : "memory");
            asm volatile(
                "cp.async.bulk.shared::cluster.global.mbarrier::complete_tx::bytes "
                "[%0], [%1], %2, [%3];"
                :: "r"(dst), "l"(src), "r"(CHBYTES), "r"(bar) : "memory");
            if (h + NSTAGE + PF < nch)
                l2_prefetch((const void*)
                            (xb + (size_t)(t0 + (h + NSTAGE + PF) * CHROWS) * 128));
        }

        if (h & 1) {
            const int lb = h >> 1;
            if (lb == 0)
                open_fin = fin;      // partials for outputs [t0-32, t0)
            else
                outb[t0 + lb * 32 - 32 + m] = fin * inv;
        }
    }
    // acc holds partials for outputs [t1-32, t1) (lane m -> t1-32+m)

    sopen[w * 32 + m] = open_fin;

    if (w == WPB - 1) {
        // CTA-edge warp: close boundary via guarded global halo rows
        const float* xbl = xb + 4 * m;
        #pragma unroll 8
        for (int k = 0; k < 32; ++k) {
            const int t = t1 + k;
            float4 v = make_float4(0.f, 0.f, 0.f, 0.f);
            if (t < T) v = *(const float4*)(xbl + (size_t)t * 128);
            float tot = (v.x + v.y) + (v.z + v.w);
            float a = fmaf(v.x, f0, fmaf(v.y, f1, fmaf(v.z, f2, v.w * f3)));
            float cc = tot - a;
            int r = (k - m) & 31;
            float u1 = __shfl_sync(0xffffffffu, a, r);
            float u2 = __shfl_sync(0xffffffffu, cc, (r + 31) & 31);
            bool wrap = (r == 0);
            float closed = acc + u2;
            fin = wrap ? closed : fin;
            acc = wrap ? u1 : acc + (u1 + u2);
        }
        outb[t1 - 32 + m] = fin * inv;
    }

    __syncthreads();

    if (w < WPB - 1) {
        float final = acc + sopen[(w + 1) * 32 + m];
        outb[t1 - 32 + m] = final * inv;
    }
}

extern "C" void kernel_launch(void* const* d_in, const int* in_sizes, int n_in,
                              void* d_out, int out_size)
{
    const float* x = (const float*)d_in[0];
    float* out = (float*)d_out;

    const int T = 100000;
    const int B = out_size / T;                    // 16

    // Host-side delay split mask (same libm as numpy's round path).
    double q = sin(0.5235987755982988);
    uint32_t cm[4] = {0u, 0u, 0u, 0u};
    for (int l = 0; l < 32; ++l) {
        uint32_t nib = 0u;
        for (int j = 0; j < 4; ++j) {
            int s = 4 * l + j;
            int d = (int)rint((double)s * q / 2.0);
            if (d == l) nib |= (1u << j);
        }
        cm[l >> 3] |= nib << ((l & 7) * 4);
    }
    uint4 cmask = make_uint4(cm[0], cm[1], cm[2], cm[3]);

    static int smem_set = 0;
    if (!smem_set) {
        cudaFuncSetAttribute(das11_kernel,
                             cudaFuncAttributeMaxDynamicSharedMemorySize,
                             SM_TOTAL);
        smem_set = 1;
    }

    const int grid = B * CPB;                      // 144 CTAs
    das11_kernel<<<grid, NTHREADS, SM_TOTAL>>>(x, out, T, cmask);
}

// round 15
// speedup vs baseline: 1.0101x; 1.0101x over previous
#include <cuda_runtime.h>
#include <cuda_bf16.h>
#include <math.h>
#include <stdint.h>

// DelayAndSum: out[b,t] = (1/128) * sum_s x[b, t+d_s, s], zero past T.
// d_s = rint(s*sin(0.5235987755982988)/2) in [0,32].
//
// R15 = R9 champion (8 warps/CTA, per-warp 3-stage x 8 KB cp.async.bulk
// SMEM ring, ring-accumulator compute, 144 CTAs = 9/batch) with the block
// partition equidistributed: warp wb owns blocks [floor(wb*3125/72),
// floor((wb+1)*3125/72)), so the 29 long (44-block) warps are spread evenly
// across CTAs instead of clustering in CTAs 0-3 of each batch (R9's ~2.3%
// straggler tail on 4 SMs/batch).

#define NTHREADS  256
#define WPB       8
#define CPB       9                   // CTAs per batch
#define WPBATCH   (WPB * CPB)         // 72
#define BPB       3125                // 32-row blocks per batch (T/32)
#define CHROWS    16
#define CHBYTES   (CHROWS * 512)      // 8192
#define NSTAGE    3

#define SM_STAGES   0
#define SM_SOPEN    (WPB * NSTAGE * CHBYTES)          // 196608
#define SM_MBAR     (SM_SOPEN + WPB * 32 * 4)         // 197632
#define SM_TOTAL    (SM_MBAR + WPB * NSTAGE * 8)      // 197824

__device__ __forceinline__ void mbar_wait(uint32_t mbar, uint32_t phase) {
    asm volatile(
        "{\n\t"
        ".reg .pred P1;\n\t"
        "WAIT_LOOP_%=:\n\t"
        "mbarrier.try_wait.parity.acquire.cta.shared::cta.b64 P1, [%0], %1, 0x989680;\n\t"
        "@P1 bra.uni WAIT_DONE_%=;\n\t"
        "bra.uni WAIT_LOOP_%=;\n\t"
        "WAIT_DONE_%=:\n\t"
        "}"
        :: "r"(mbar), "r"(phase) : "memory");
}

__global__ __launch_bounds__(NTHREADS, 1)
void das12_kernel(const float* __restrict__ x, float* __restrict__ out,
                  int T, uint4 cmask)
{
    extern __shared__ char smem[];
    const uint32_t smem_u32 = (uint32_t)__cvta_generic_to_shared(smem);

    const int w  = threadIdx.x >> 5;
    const int m  = threadIdx.x & 31;
    const int c  = blockIdx.x;
    const int b  = c / CPB;
    const int cb = c % CPB;
    const int wb = cb * WPB + w;

    // equidistributed partition: long warps spread evenly across CTAs
    const int start_blk = (wb * BPB) / WPBATCH;
    const int end_blk   = ((wb + 1) * BPB) / WPBATCH;
    const int nblk      = end_blk - start_blk;     // 43 or 44
    const int t0  = start_blk * 32;
    const int t1  = t0 + nblk * 32;
    const int nch = nblk * 2;                      // 16-row chunks

    const float* __restrict__ xb = x + (size_t)b * (size_t)T * 128;
    float* __restrict__ outb = out + (size_t)b * T;
    float* sopen = (float*)(smem + SM_SOPEN);

    const uint32_t mbar0 = smem_u32 + SM_MBAR + w * (NSTAGE * 8);
    const uint32_t stg0  = smem_u32 + SM_STAGES + w * (NSTAGE * CHBYTES);

    // per-lane split mask: bit j set <=> d(4m+j) == m (row t+m), else d==m+1
    uint32_t mword = (m < 8)  ? cmask.x :
                     (m < 16) ? cmask.y :
                     (m < 24) ? cmask.z : cmask.w;
    uint32_t bits = (mword >> ((m & 7) * 4)) & 0xFu;
    const float f0 = (bits & 1u) ? 1.f : 0.f;
    const float f1 = (bits & 2u) ? 1.f : 0.f;
    const float f2 = (bits & 4u) ? 1.f : 0.f;
    const float f3 = (bits & 8u) ? 1.f : 0.f;
    const float inv = 1.0f / 128.0f;

    // init this warp's mbarriers
    if (m == 0) {
        #pragma unroll
        for (int s = 0; s < NSTAGE; ++s)
            asm volatile("mbarrier.init.shared.b64 [%0], %1;"
                         :: "r"(mbar0 + s * 8), "r"(1) : "memory");
    }
    __syncwarp();

    // prologue: fill the 3-stage pipeline
    if (m == 0) {
        #pragma unroll
        for (int h = 0; h < NSTAGE; ++h) {
            uint32_t bar = mbar0 + h * 8;
            uint32_t dst = stg0 + h * CHBYTES;
            const void* src = (const void*)(xb + (size_t)(t0 + h * CHROWS) * 128);
            asm volatile("mbarrier.arrive.expect_tx.shared.b64 _, [%0], %1;"
                         :: "r"(bar), "r"(CHBYTES) : "memory");
            asm volatile(
                "cp.async.bulk.shared::cluster.global.mbarrier::complete_tx::bytes "
                "[%0], [%1], %2, [%3];"
                :: "r"(dst), "l"(src), "r"(CHBYTES), "r"(bar) : "memory");
        }
    }

    float acc = 0.f, fin = 0.f, open_fin = 0.f;

    #pragma unroll 1
    for (int h = 0; h < nch; ++h) {
        const int s  = h % NSTAGE;
        const uint32_t ph = (uint32_t)((h / NSTAGE) & 1);
        mbar_wait(mbar0 + s * 8, ph);

        const float4* sb = (const float4*)(smem + w * (NSTAGE * CHBYTES)
                                                + s * CHBYTES) + m;
        const int kbase = (h & 1) << 4;
        #pragma unroll
        for (int i = 0; i < CHROWS; ++i) {
            float4 v = sb[i * 32];
            float tot = (v.x + v.y) + (v.z + v.w);
            float a = fmaf(v.x, f0, fmaf(v.y, f1, fmaf(v.z, f2, v.w * f3)));
            float cc = tot - a;
            int k = kbase + i;
            int r = (k - m) & 31;
            float u1 = __shfl_sync(0xffffffffu, a, r);
            float u2 = __shfl_sync(0xffffffffu, cc, (r + 31) & 31);
            bool wrap = (r == 0);
            float closed = acc + u2;
            fin = wrap ? closed : fin;
            acc = wrap ? u1 : acc + (u1 + u2);
        }
        __syncwarp();

        // reuse this stage for chunk h+NSTAGE
        if (h + NSTAGE < nch && m == 0) {
            asm volatile("fence.proxy.async.shared::cta;" ::: "memory");
            uint32_t bar = mbar0 + s * 8;
            uint32_t dst = stg0 + s * CHBYTES;
            const void* src =
                (const void*)(xb + (size_t)(t0 + (h + NSTAGE) * CHROWS) * 128);
            asm volatile("mbarrier.arrive.expect_tx.shared.b64 _, [%0], %1;"
                         :: "r"(bar), "r"(CHBYTES) : "memory");
            asm volatile(
                "cp.async.bulk.shared::cluster.global.mbarrier::complete_tx::bytes "
                "[%0], [%1], %2, [%3];"
                :: "r"(dst), "l"(src), "r"(CHBYTES), "r"(bar) : "memory");
        }

        if (h & 1) {
            const int lb = h >> 1;
            if (lb == 0)
                open_fin = fin;      // partials for outputs [t0-32, t0)
            else
                outb[t0 + lb * 32 - 32 + m] = fin * inv;
        }
    }
    // acc holds partials for outputs [t1-32, t1) (lane m -> t1-32+m)

    sopen[w * 32 + m] = open_fin;

    if (w == WPB - 1) {
        // CTA-edge warp: close boundary via guarded global halo rows
        const float* xbl = xb + 4 * m;
        #pragma unroll 8
        for (int k = 0; k < 32; ++k) {
            const int t = t1 + k;
            float4 v = make_float4(0.f, 0.f, 0.f, 0.f);
            if (t < T) v = *(const float4*)(xbl + (size_t)t * 128);
            float tot = (v.x + v.y) + (v.z + v.w);
            float a = fmaf(v.x, f0, fmaf(v.y, f1, fmaf(v.z, f2, v.w * f3)));
            float cc = tot - a;
            int r = (k - m) & 31;
            float u1 = __shfl_sync(0xffffffffu, a, r);
            float u2 = __shfl_sync(0xffffffffu, cc, (r + 31) & 31);
            bool wrap = (r == 0);
            float closed = acc + u2;
            fin = wrap ? closed : fin;
            acc = wrap ? u1 : acc + (u1 + u2);
        }
        outb[t1 - 32 + m] = fin * inv;
    }

    __syncthreads();

    if (w < WPB - 1) {
        // next warp (same CTA, contiguous blocks) supplies complementary partials
        float final = acc + sopen[(w + 1) * 32 + m];
        outb[t1 - 32 + m] = final * inv;
    }
}

extern "C" void kernel_launch(void* const* d_in, const int* in_sizes, int n_in,
                              void* d_out, int out_size)
{
    const float* x = (const float*)d_in[0];
    float* out = (float*)d_out;

    const int T = 100000;
    const int B = out_size / T;                    // 16

    // Host-side delay split mask (same libm as numpy's round path).
    double q = sin(0.5235987755982988);
    uint32_t cm[4] = {0u, 0u, 0u, 0u};
    for (int l = 0; l < 32; ++l) {
        uint32_t nib = 0u;
        for (int j = 0; j < 4; ++j) {
            int s = 4 * l + j;
            int d = (int)rint((double)s * q / 2.0);
            if (d == l) nib |= (1u << j);
        }
        cm[l >> 3] |= nib << ((l & 7) * 4);
    }
    uint4 cmask = make_uint4(cm[0], cm[1], cm[2], cm[3]);

    static int smem_set = 0;
    if (!smem_set) {
        cudaFuncSetAttribute(das12_kernel,
                             cudaFuncAttributeMaxDynamicSharedMemorySize,
                             SM_TOTAL);
        smem_set = 1;
    }

    const int grid = B * CPB;                      // 144 CTAs
    das12_kernel<<<grid, NTHREADS, SM_TOTAL>>>(x, out, T, cmask);
}